// round 16
// baseline (speedup 1.0000x reference)
#include <cuda_runtime.h>
#include <cuda_fp16.h>

#define B 8
#define N 2048
#define D 64
#define ALPHA 0.2f

// Scratch: h fp16 [B,N,D]; per-row exp packs (e^s, e^{(a-1)s}) / (e^t, e^{at});
// colsum accumulators + flags.
__device__ __align__(16) __half  g_hh[B * N * D];
__device__ __align__(16) float2  g_se[B * N];
__device__ __align__(16) float2  g_te[B * N];
__device__ __align__(16) float   g_S[B * D];    // finalized colsums
__device__ __align__(16) float   g_S2[B * D];   // atomic accumulators (zero-init, self-resetting)
__device__ int g_cnt[B];                        // zero-init, self-resetting

// Fused: h = x@W (fp16 out), colsums S (atomics + last-block finalize),
// s/t row-dots + exp packs. Block (64,4); 32 rows/block; grid = B*N/32 = 512.
__global__ __launch_bounds__(256) void k_h(const float* __restrict__ x,
                                           const float* __restrict__ W,
                                           const float* __restrict__ a) {
    __shared__ float Ws[64 * 64];
    __shared__ float xs[32 * 64];
    __shared__ float red[4][64];
    __shared__ float redS[8][4][2];
    __shared__ float redT[8][4][2];
    __shared__ int isLast;
    int tx = threadIdx.x, ty = threadIdx.y;
    int tid = ty * 64 + tx;

    const float4* W4 = (const float4*)W;
    float4* Ws4 = (float4*)Ws;
    for (int k = tid; k < 1024; k += 256) Ws4[k] = W4[k];
    int rowBase = blockIdx.x * 32;               // flattened over B*N (32 | N)
    int b = rowBase / N;
    const float4* x4 = ((const float4*)x) + rowBase * 16;
    float4* xs4 = (float4*)xs;
    for (int k = tid; k < 512; k += 256) xs4[k] = x4[k];
    __syncthreads();

    float a0 = a[tx];
    float a1 = a[64 + tx];
    float accs[8];
#pragma unroll
    for (int rt = 0; rt < 8; rt++) accs[rt] = 0.f;
#pragma unroll
    for (int i4 = 0; i4 < 16; i4++) {
        float w0 = Ws[(i4 * 4 + 0) * 64 + tx];
        float w1 = Ws[(i4 * 4 + 1) * 64 + tx];
        float w2 = Ws[(i4 * 4 + 2) * 64 + tx];
        float w3 = Ws[(i4 * 4 + 3) * 64 + tx];
#pragma unroll
        for (int rt = 0; rt < 8; rt++) {
            float4 xv = xs4[(rt * 4 + ty) * 16 + i4];
            accs[rt] = fmaf(xv.x, w0, accs[rt]);
            accs[rt] = fmaf(xv.y, w1, accs[rt]);
            accs[rt] = fmaf(xv.z, w2, accs[rt]);
            accs[rt] = fmaf(xv.w, w3, accs[rt]);
        }
    }
    float part = 0.f;
#pragma unroll
    for (int rt = 0; rt < 8; rt++) {
        g_hh[(rowBase + rt * 4 + ty) * 64 + tx] = __float2half_rn(accs[rt]);
        part += accs[rt];
    }
    int lane = tid & 31, half = tx >> 5;
#pragma unroll
    for (int rt = 0; rt < 8; rt++) {
        float sp = accs[rt] * a0;
        float tp = accs[rt] * a1;
#pragma unroll
        for (int o = 16; o > 0; o >>= 1) {
            sp += __shfl_xor_sync(0xffffffffu, sp, o);
            tp += __shfl_xor_sync(0xffffffffu, tp, o);
        }
        if (lane == 0) { redS[rt][ty][half] = sp; redT[rt][ty][half] = tp; }
    }
    red[ty][tx] = part;
    __syncthreads();
    if (tid < 32) {
        int rt = tid >> 2, tyy = tid & 3;
        float s = redS[rt][tyy][0] + redS[rt][tyy][1];
        float t = redT[rt][tyy][0] + redT[rt][tyy][1];
        int r = rowBase + rt * 4 + tyy;
        // (e^s, e^{(alpha-1)s}) so  f1*max(e^t, r*e^{at}) = max(e^{s+t}, e^{a(s+t)})
        g_se[r] = make_float2(__expf(s), __expf((ALPHA - 1.f) * s));
        g_te[r] = make_float2(__expf(t), __expf(ALPHA * t));
    }
    if (ty == 0) {
        float ssum = red[0][tx] + red[1][tx] + red[2][tx] + red[3][tx];
        atomicAdd(&g_S2[b * 64 + tx], ssum);
    }
    __threadfence();             // order this thread's g_S2 atomic
    __syncthreads();             // ...and everyone's, before the signal
    if (tid == 0) {
        int old = atomicAdd(&g_cnt[b], 1);
        isLast = (old == 63);
        if (isLast) __threadfence();   // acquire before reading g_S2
    }
    __syncthreads();
    if (isLast && tid < 64) {
        g_S[b * 64 + tid] = g_S2[b * 64 + tid];
        g_S2[b * 64 + tid] = 0.f;
        if (tid == 0) g_cnt[b] = 0;
    }
}

// One block per row i. Phase 1: atomic-free sorted neighbor compaction.
// Phase 2: warp b = batch b; 8 neighbors/warp-iter: sub = lane>>2 picks the
// neighbor, d4 = lane&3 picks a 32B chunk (16 dims) of the 128B fp16 row.
// c = fma(e^s, max(e^t, e^{(a-1)s} e^{at}), -1), computed per-lane.
__global__ __launch_bounds__(256, 4) void k_main(const float* __restrict__ adj,
                                                 const float* __restrict__ bias,
                                                 float* __restrict__ out) {
    __shared__ unsigned short nbr[N + 8];
    __shared__ float sh_f1[8], sh_r[8];
    __shared__ int sh_wtot[8], sh_wbase[8], sh_cnt;
    int i = blockIdx.x, tid = threadIdx.x;
    int wid = tid >> 5, lane = tid & 31;

    if (tid < 8) {
        float2 se = g_se[tid * N + i];
        sh_f1[tid] = se.x; sh_r[tid] = se.y;
    }

    // ---- Phase 1: scan 8 contiguous adj entries per thread ----
    const float4* arow4 = (const float4*)(adj + (size_t)i * N);
    float4 v0 = arow4[tid * 2];
    float4 v1 = arow4[tid * 2 + 1];
    int j0 = tid * 8;
    unsigned bm = 0;
    bm |= (v0.x != 0.f) ? 1u : 0u;
    bm |= (v0.y != 0.f) ? 2u : 0u;
    bm |= (v0.z != 0.f) ? 4u : 0u;
    bm |= (v0.w != 0.f) ? 8u : 0u;
    bm |= (v1.x != 0.f) ? 16u : 0u;
    bm |= (v1.y != 0.f) ? 32u : 0u;
    bm |= (v1.z != 0.f) ? 64u : 0u;
    bm |= (v1.w != 0.f) ? 128u : 0u;
    if ((unsigned)(i - j0) < 8u) bm |= 1u << (i - j0);   // forced diagonal
    int lc = __popc(bm);
    int pre = lc;
#pragma unroll
    for (int o = 1; o < 32; o <<= 1) {
        int u = __shfl_up_sync(0xffffffffu, pre, o);
        if (lane >= o) pre += u;
    }
    if (lane == 31) sh_wtot[wid] = pre;
    __syncthreads();
    if (tid == 0) {
        int run = 0;
#pragma unroll
        for (int w = 0; w < 8; w++) { sh_wbase[w] = run; run += sh_wtot[w]; }
        sh_cnt = run;
    }
    __syncthreads();
    int base = sh_wbase[wid] + pre - lc;
#pragma unroll
    for (int k = 0; k < 8; k++) {
        if (bm & (1u << k))
            nbr[base + __popc(bm & ((1u << k) - 1u))] = (unsigned short)(j0 + k);
    }
    __syncthreads();
    int cnt = sh_cnt;

    // ---- Phase 2: gather-accumulate, 8 neighbors per warp-iteration ----
    int b = wid, sub = lane >> 2, d4 = lane & 3;
    float f1 = sh_f1[b], rr = sh_r[b];
    const float2* teb = (const float2*)g_te + b * N;
    const char* hb = (const char*)g_hh + (size_t)(b * N * D) * 2 + d4 * 32;
    float acc[16];
#pragma unroll
    for (int q = 0; q < 16; q++) acc[q] = 0.f;
    float z = 0.f;
    int full = cnt & ~7;
#pragma unroll 4
    for (int k0 = 0; k0 < full; k0 += 8) {
        int j = (int)nbr[k0 + sub];
        float2 te = teb[j];
        const char* hp = hb + (j << 7);
        uint4 u0 = *(const uint4*)hp;          // dims d4*16 .. +7
        uint4 u1 = *(const uint4*)(hp + 16);   // dims d4*16+8 .. +15
        float c = fmaf(f1, fmaxf(te.x, rr * te.y), -1.f);
        float2 q0 = __half22float2(*(const __half2*)&u0.x);
        float2 q1 = __half22float2(*(const __half2*)&u0.y);
        float2 q2 = __half22float2(*(const __half2*)&u0.z);
        float2 q3 = __half22float2(*(const __half2*)&u0.w);
        float2 q4 = __half22float2(*(const __half2*)&u1.x);
        float2 q5 = __half22float2(*(const __half2*)&u1.y);
        float2 q6 = __half22float2(*(const __half2*)&u1.z);
        float2 q7 = __half22float2(*(const __half2*)&u1.w);
        acc[0]  = fmaf(c, q0.x, acc[0]);  acc[1]  = fmaf(c, q0.y, acc[1]);
        acc[2]  = fmaf(c, q1.x, acc[2]);  acc[3]  = fmaf(c, q1.y, acc[3]);
        acc[4]  = fmaf(c, q2.x, acc[4]);  acc[5]  = fmaf(c, q2.y, acc[5]);
        acc[6]  = fmaf(c, q3.x, acc[6]);  acc[7]  = fmaf(c, q3.y, acc[7]);
        acc[8]  = fmaf(c, q4.x, acc[8]);  acc[9]  = fmaf(c, q4.y, acc[9]);
        acc[10] = fmaf(c, q5.x, acc[10]); acc[11] = fmaf(c, q5.y, acc[11]);
        acc[12] = fmaf(c, q6.x, acc[12]); acc[13] = fmaf(c, q6.y, acc[13]);
        acc[14] = fmaf(c, q7.x, acc[14]); acc[15] = fmaf(c, q7.y, acc[15]);
        z += c;
    }
    if (full < cnt) {            // tail: 1-7 neighbors, predicated
        int k = full + sub;
        bool valid = k < cnt;
        int j = valid ? (int)nbr[k] : 0;
        float2 te = teb[j];
        const char* hp = hb + (j << 7);
        uint4 u0 = *(const uint4*)hp;
        uint4 u1 = *(const uint4*)(hp + 16);
        float c = fmaf(f1, fmaxf(te.x, rr * te.y), -1.f);
        c = valid ? c : 0.f;
        float2 q0 = __half22float2(*(const __half2*)&u0.x);
        float2 q1 = __half22float2(*(const __half2*)&u0.y);
        float2 q2 = __half22float2(*(const __half2*)&u0.z);
        float2 q3 = __half22float2(*(const __half2*)&u0.w);
        float2 q4 = __half22float2(*(const __half2*)&u1.x);
        float2 q5 = __half22float2(*(const __half2*)&u1.y);
        float2 q6 = __half22float2(*(const __half2*)&u1.z);
        float2 q7 = __half22float2(*(const __half2*)&u1.w);
        acc[0]  = fmaf(c, q0.x, acc[0]);  acc[1]  = fmaf(c, q0.y, acc[1]);
        acc[2]  = fmaf(c, q1.x, acc[2]);  acc[3]  = fmaf(c, q1.y, acc[3]);
        acc[4]  = fmaf(c, q2.x, acc[4]);  acc[5]  = fmaf(c, q2.y, acc[5]);
        acc[6]  = fmaf(c, q3.x, acc[6]);  acc[7]  = fmaf(c, q3.y, acc[7]);
        acc[8]  = fmaf(c, q4.x, acc[8]);  acc[9]  = fmaf(c, q4.y, acc[9]);
        acc[10] = fmaf(c, q5.x, acc[10]); acc[11] = fmaf(c, q5.y, acc[11]);
        acc[12] = fmaf(c, q6.x, acc[12]); acc[13] = fmaf(c, q6.y, acc[13]);
        acc[14] = fmaf(c, q7.x, acc[14]); acc[15] = fmaf(c, q7.y, acc[15]);
        z += c;
    }
    // reduce across the 8 sub-groups (lane bits 2,3,4)
#pragma unroll
    for (int o = 4; o <= 16; o <<= 1) {
#pragma unroll
        for (int q = 0; q < 16; q++)
            acc[q] += __shfl_xor_sync(0xffffffffu, acc[q], o);
        z += __shfl_xor_sync(0xffffffffu, z, o);
    }
    if (sub == 0) {                       // lanes 0-3: dims d4*16 .. d4*16+15
        float inv = 1.f / ((float)N + z);
        const float4* S4 = (const float4*)&g_S[b * 64 + d4 * 16];
        const float4* b4 = (const float4*)&bias[d4 * 16];
        float4* op = (float4*)(out + (size_t)(b * N + i) * 64 + d4 * 16);
#pragma unroll
        for (int v = 0; v < 4; v++) {
            float4 S = S4[v], bb = b4[v], o4;
            o4.x = (S.x + acc[v * 4 + 0]) * inv + bb.x;
            o4.y = (S.y + acc[v * 4 + 1]) * inv + bb.y;
            o4.z = (S.z + acc[v * 4 + 2]) * inv + bb.z;
            o4.w = (S.w + acc[v * 4 + 3]) * inv + bb.w;
            op[v] = o4;
        }
    }
}

extern "C" void kernel_launch(void* const* d_in, const int* in_sizes, int n_in,
                              void* d_out, int out_size) {
    const float* x    = (const float*)d_in[0];  // [B,N,64]
    const float* adj  = (const float*)d_in[1];  // [N,N]
    const float* W    = (const float*)d_in[2];  // [64,64]
    const float* a    = (const float*)d_in[3];  // [128,1]
    const float* bias = (const float*)d_in[4];  // [64]
    float* out = (float*)d_out;                 // [B,N,64]

    k_h<<<(B * N) / 32, dim3(64, 4)>>>(x, W, a);
    k_main<<<N, 256>>>(adj, bias, out);
}